// round 9
// baseline (speedup 1.0000x reference)
#include <cuda_runtime.h>
#include <cuda_bf16.h>
#include <math.h>

// ---- constants ----
#define TT   2048
#define DM   1024
#define NH   16
#define HD   64
#define NBLK 32
#define NSEL 16

// ---- static scratch ----
__device__ float g_q   [TT * DM];
__device__ float g_k   [TT * HD];
__device__ float g_v   [TT * HD];
__device__ float g_gate[TT * 48];
__device__ float g_kc  [NBLK * HD];
__device__ float g_vc  [NBLK * HD];
__device__ float g_ocmp[TT * DM];
__device__ float g_o   [TT * DM];
__device__ int   g_sel [TT * NSEL];
// pre-split K/V (bf16 hi/lo); V stored transposed [d][t]
__device__ __nv_bfloat16 g_kh[TT * HD];
__device__ __nv_bfloat16 g_kl[TT * HD];
__device__ __nv_bfloat16 g_vhT[HD * TT];
__device__ __nv_bfloat16 g_vlT[HD * TT];

// ======================================================================
// GEMM: C[M,N] = A[M,1024] * B[N,1024]^T.  BM=128 BN=64 BK=16, 256 thr.
// ======================================================================
__device__ __forceinline__ void gemm_body(const float* __restrict__ A,
                                          const float* __restrict__ B,
                                          float* __restrict__ C, int N)
{
    __shared__ float As[16][132];
    __shared__ float Bs[16][68];
    const int K = 1024;
    int tid = threadIdx.x;
    int tr = tid >> 4, tc = tid & 15;
    int row0 = blockIdx.y * 128, col0 = blockIdx.x * 64;
    float acc[8][4];
#pragma unroll
    for (int i = 0; i < 8; i++)
#pragma unroll
        for (int j = 0; j < 4; j++) acc[i][j] = 0.f;

    int ar = tid >> 2, aq = tid & 3;

    for (int kt = 0; kt < K; kt += 16) {
#pragma unroll
        for (int i = 0; i < 2; i++) {
            int r = ar + i * 64;
            float4 va = *(const float4*)(A + (size_t)(row0 + r) * K + kt + aq * 4);
            As[aq*4+0][r] = va.x; As[aq*4+1][r] = va.y;
            As[aq*4+2][r] = va.z; As[aq*4+3][r] = va.w;
        }
        {
            float4 vb = make_float4(0.f,0.f,0.f,0.f);
            if (col0 + ar < N)
                vb = *(const float4*)(B + (size_t)(col0 + ar) * K + kt + aq * 4);
            Bs[aq*4+0][ar] = vb.x; Bs[aq*4+1][ar] = vb.y;
            Bs[aq*4+2][ar] = vb.z; Bs[aq*4+3][ar] = vb.w;
        }
        __syncthreads();
#pragma unroll
        for (int k = 0; k < 16; k++) {
            float4 a0 = *(const float4*)(&As[k][tr*8]);
            float4 a1 = *(const float4*)(&As[k][tr*8+4]);
            float4 b  = *(const float4*)(&Bs[k][tc*4]);
            float av[8] = {a0.x,a0.y,a0.z,a0.w,a1.x,a1.y,a1.z,a1.w};
            float bv[4] = {b.x,b.y,b.z,b.w};
#pragma unroll
            for (int i = 0; i < 8; i++)
#pragma unroll
                for (int j = 0; j < 4; j++) acc[i][j] += av[i] * bv[j];
        }
        __syncthreads();
    }
    if (col0 + tc*4 < N) {
#pragma unroll
        for (int i = 0; i < 8; i++) {
            float4 o = make_float4(acc[i][0], acc[i][1], acc[i][2], acc[i][3]);
            *(float4*)(C + (size_t)(row0 + tr*8 + i) * N + col0 + tc*4) = o;
        }
    }
}

__global__ __launch_bounds__(256) void proj_gemm_kernel(
    const float* __restrict__ x,
    const float* __restrict__ Wq, const float* __restrict__ Wk,
    const float* __restrict__ Wv, const float* __restrict__ Wg)
{
    const float* B; float* C; int N;
    if      (blockIdx.z == 0) { B = Wq; C = g_q;    N = 1024; }
    else if (blockIdx.z == 1) { B = Wk; C = g_k;    N = 64;   }
    else if (blockIdx.z == 2) { B = Wv; C = g_v;    N = 64;   }
    else                      { B = Wg; C = g_gate; N = 48;   }
    if ((int)blockIdx.x * 64 >= N) return;
    gemm_body(x, B, C, N);
}

__global__ __launch_bounds__(256) void out_gemm_kernel(
    const float* __restrict__ Wo, float* __restrict__ out)
{
    gemm_body(g_o, Wo, out, 1024);
}

// ======================================================================
// Block mean pool
// ======================================================================
__global__ void pool_kernel()
{
    int b = blockIdx.x, d = threadIdx.x;
    float sk = 0.f, sv = 0.f;
    for (int j = 0; j < 64; j++) {
        sk += g_k[(b*64 + j)*64 + d];
        sv += g_v[(b*64 + j)*64 + d];
    }
    g_kc[b*64 + d] = sk * (1.f/64.f);
    g_vc[b*64 + d] = sv * (1.f/64.f);
}

// ======================================================================
// Pre-split K/V into bf16 hi/lo (V transposed)
// ======================================================================
__global__ __launch_bounds__(256) void split_kv_kernel()
{
    int i = blockIdx.x * 256 + threadIdx.x;   // 131072 total
    int t = i >> 6, d = i & 63;
    float k = g_k[i], v = g_v[i];
    __nv_bfloat16 kh = __float2bfloat16(k);
    __nv_bfloat16 kl = __float2bfloat16(k - __bfloat162float(kh));
    g_kh[i] = kh; g_kl[i] = kl;
    __nv_bfloat16 vh = __float2bfloat16(v);
    __nv_bfloat16 vl = __float2bfloat16(v - __bfloat162float(vh));
    g_vhT[d * TT + t] = vh; g_vlT[d * TT + t] = vl;
}

// ======================================================================
// Compressed attention + top-k selection. CTA/token, 256 thr.
// ======================================================================
__global__ __launch_bounds__(256) void cmp_attn_kernel()
{
    int t = blockIdx.x;
    int tid = threadIdx.x, lane = tid & 31, w = tid >> 5;
    __shared__ float sKC[32*65], sVC[32*65];
    __shared__ float sP[16*36];
    __shared__ float simp[32];

    for (int i = tid; i < 2048; i += 256) {
        int c = i >> 6, d = i & 63;
        sKC[c*65 + d] = g_kc[i];
        sVC[c*65 + d] = g_vc[i];
    }
    __syncthreads();

    int nv = (t + 1) >> 6;
    int h0 = w*2, h1 = w*2 + 1;
    size_t qb = (size_t)t * 1024;
    float q00 = g_q[qb + h0*64 + lane],      q01 = g_q[qb + h0*64 + 32 + lane];
    float q10 = g_q[qb + h1*64 + lane],      q11 = g_q[qb + h1*64 + 32 + lane];

    for (int c = 0; c < nv; c++) {
        float k0 = sKC[c*65 + lane], k1 = sKC[c*65 + 32 + lane];
        float a = q00*k0 + q01*k1;
        float b = q10*k0 + q11*k1;
        for (int o = 16; o; o >>= 1) {
            a += __shfl_xor_sync(~0u, a, o);
            b += __shfl_xor_sync(~0u, b, o);
        }
        if (lane == 0) { sP[h0*36 + c] = a*0.125f; sP[h1*36 + c] = b*0.125f; }
    }
    __syncwarp();
#pragma unroll
    for (int hh = 0; hh < 2; hh++) {
        int h = h0 + hh;
        float v = (lane < nv) ? sP[h*36 + lane] : -INFINITY;
        float mx = v;
        for (int o = 16; o; o >>= 1) mx = fmaxf(mx, __shfl_xor_sync(~0u, mx, o));
        float e = (lane < nv) ? __expf(v - mx) : 0.f;
        float sm = e;
        for (int o = 16; o; o >>= 1) sm += __shfl_xor_sync(~0u, sm, o);
        sP[h*36 + lane] = (nv > 0) ? e / sm : 0.f;
    }
    __syncwarp();
    float o00=0,o01=0,o10=0,o11=0;
    for (int c = 0; c < nv; c++) {
        float p0 = sP[h0*36 + c], p1 = sP[h1*36 + c];
        float v0 = sVC[c*65 + lane], v1 = sVC[c*65 + 32 + lane];
        o00 += p0*v0; o01 += p0*v1; o10 += p1*v0; o11 += p1*v1;
    }
    float gc0 = 1.f/(1.f + __expf(-g_gate[t*48 + h0*3]));
    float gc1 = 1.f/(1.f + __expf(-g_gate[t*48 + h1*3]));
    g_ocmp[qb + h0*64 + lane]      = o00*gc0;
    g_ocmp[qb + h0*64 + 32 + lane] = o01*gc0;
    g_ocmp[qb + h1*64 + lane]      = o10*gc1;
    g_ocmp[qb + h1*64 + 32 + lane] = o11*gc1;
    __syncthreads();

    if (w == 0) {
        float imp = 0.f;
        for (int h = 0; h < 16; h++) imp += sP[h*36 + lane];
        int cur = t >> 6;
        float val;
        if (lane == 0 || lane == cur) val = 1e38f;
        else if (lane <= cur)         val = imp;
        else                          val = -1e30f;
        simp[lane] = val;
        __syncwarp();
        int rank = 0;
        for (int c = 0; c < 32; c++) {
            float vc = simp[c];
            if (vc > val || (vc == val && c < lane)) rank++;
        }
        unsigned msk = __ballot_sync(~0u, rank < NSEL);
        if (rank < NSEL) {
            int pos = __popc(msk & ((1u << lane) - 1));
            g_sel[t*NSEL + pos] = lane;
        }
    }
}

// ======================================================================
// bf16 helpers
// ======================================================================
__device__ __forceinline__ void bfsplit2(float x0, float x1, unsigned& h, unsigned& l)
{
    __nv_bfloat162 hh = __floats2bfloat162_rn(x0, x1);
    float r0 = x0 - __bfloat162float(hh.x);
    float r1 = x1 - __bfloat162float(hh.y);
    __nv_bfloat162 ll = __floats2bfloat162_rn(r0, r1);
    h = *(unsigned*)&hh; l = *(unsigned*)&ll;
}
__device__ __forceinline__ void mma16(float* c, const unsigned* a, unsigned b0, unsigned b1)
{
    asm("mma.sync.aligned.m16n8k16.row.col.f32.bf16.bf16.f32 "
        "{%0,%1,%2,%3}, {%4,%5,%6,%7}, {%8,%9}, {%0,%1,%2,%3};"
        : "+f"(c[0]), "+f"(c[1]), "+f"(c[2]), "+f"(c[3])
        : "r"(a[0]), "r"(a[1]), "r"(a[2]), "r"(a[3]), "r"(b0), "r"(b1));
}

// ======================================================================
// Selected block-sparse attention — direct-LDG operand fetch.
// CTA = 1 token (swizzled for same-SM token locality), 4 warps;
// warp w owns keys [w*16, w*16+16) of each selected block.
// No staging smem, no per-block syncs; K/V/P fragments never touch smem.
// ======================================================================
__global__ __launch_bounds__(128) void sel_attn_kernel()
{
    __shared__ __align__(16) float sbuf[4*16*66 + 128];  // sQ first, merge later
    __shared__ int sBlk[16];

    int bid = blockIdx.x;
    int t = (bid % 148) * 14 + (bid / 148);
    if (t >= TT) return;

    int tid = threadIdx.x, lane = tid & 31, w = tid >> 5;
    int r4 = lane >> 2, q4 = lane & 3;

    float* sQ = sbuf;  // [16][68]
    for (int i = tid; i < 1024; i += 128)
        sQ[(i>>6)*68 + (i&63)] = g_q[(size_t)t*1024 + i] * 0.125f;
    if (tid < 16) sBlk[tid] = g_sel[t*16 + tid];
    __syncthreads();

    // Q A-fragments (m16k16), bf16 hi/lo, registers
    unsigned qh[16], ql[16];
#pragma unroll
    for (int kt = 0; kt < 4; kt++) {
        int k0 = kt*16 + 2*q4;
        bfsplit2(sQ[r4*68+k0],       sQ[r4*68+k0+1],       qh[kt*4+0], ql[kt*4+0]);
        bfsplit2(sQ[(r4+8)*68+k0],   sQ[(r4+8)*68+k0+1],   qh[kt*4+1], ql[kt*4+1]);
        bfsplit2(sQ[r4*68+k0+8],     sQ[r4*68+k0+9],       qh[kt*4+2], ql[kt*4+2]);
        bfsplit2(sQ[(r4+8)*68+k0+8], sQ[(r4+8)*68+k0+9],   qh[kt*4+3], ql[kt*4+3]);
    }
    __syncthreads();   // sQ fully consumed before sbuf reuse

    float o[32];
#pragma unroll
    for (int i = 0; i < 32; i++) o[i] = 0.f;
    float m0 = -INFINITY, m1 = -INFINITY, l0 = 0.f, l1 = 0.f;

    const int krow = w*16 + r4;      // this lane's key row within block (nt adds 8)
    const int d0q  = 2*q4;

    for (int bi = 0; bi < 16; bi++) {
        int kbase = sBlk[bi] * 64;

        // ---- S[16h x 16k] = Q K^T, K fragments straight from global ----
        float c[2][4] = {{0,0,0,0},{0,0,0,0}};
#pragma unroll
        for (int kt = 0; kt < 4; kt++) {
            int d0 = kt*16 + d0q;
#pragma unroll
            for (int nt = 0; nt < 2; nt++) {
                size_t ro = (size_t)(kbase + krow + nt*8) * 64 + d0;
                unsigned bh0 = *(const unsigned*)&g_kh[ro];
                unsigned bh1 = *(const unsigned*)&g_kh[ro + 8];
                unsigned bl0 = *(const unsigned*)&g_kl[ro];
                unsigned bl1 = *(const unsigned*)&g_kl[ro + 8];
                mma16(c[nt], &qh[kt*4], bh0, bh1);
                mma16(c[nt], &qh[kt*4], bl0, bl1);
                mma16(c[nt], &ql[kt*4], bh0, bh1);
            }
        }
        // causal mask: cols kg, kg+1; rows r4 (c0,c1) and r4+8 (c2,c3)
#pragma unroll
        for (int nt = 0; nt < 2; nt++) {
            int kg = kbase + w*16 + nt*8 + d0q;
            if (kg     > t) { c[nt][0] = -1e30f; c[nt][2] = -1e30f; }
            if (kg + 1 > t) { c[nt][1] = -1e30f; c[nt][3] = -1e30f; }
        }

        // ---- per-warp online softmax ----
        float lm0 = fmaxf(fmaxf(c[0][0], c[0][1]), fmaxf(c[1][0], c[1][1]));
        float lm1 = fmaxf(fmaxf(c[0][2], c[0][3]), fmaxf(c[1][2], c[1][3]));
        lm0 = fmaxf(lm0, __shfl_xor_sync(~0u, lm0, 1));
        lm0 = fmaxf(lm0, __shfl_xor_sync(~0u, lm0, 2));
        lm1 = fmaxf(lm1, __shfl_xor_sync(~0u, lm1, 1));
        lm1 = fmaxf(lm1, __shfl_xor_sync(~0u, lm1, 2));
        float mn0 = fmaxf(m0, lm0), mn1 = fmaxf(m1, lm1);
        float corr0 = __expf(m0 - mn0), corr1 = __expf(m1 - mn1);
        float p[2][4];
#pragma unroll
        for (int nt = 0; nt < 2; nt++) {
            p[nt][0] = __expf(c[nt][0] - mn0);
            p[nt][1] = __expf(c[nt][1] - mn0);
            p[nt][2] = __expf(c[nt][2] - mn1);
            p[nt][3] = __expf(c[nt][3] - mn1);
        }
        float ls0 = p[0][0] + p[0][1] + p[1][0] + p[1][1];
        float ls1 = p[0][2] + p[0][3] + p[1][2] + p[1][3];
        ls0 += __shfl_xor_sync(~0u, ls0, 1); ls0 += __shfl_xor_sync(~0u, ls0, 2);
        ls1 += __shfl_xor_sync(~0u, ls1, 1); ls1 += __shfl_xor_sync(~0u, ls1, 2);
        l0 = l0*corr0 + ls0;
        l1 = l1*corr1 + ls1;
#pragma unroll
        for (int nt = 0; nt < 8; nt++) {
            o[nt*4+0] *= corr0; o[nt*4+1] *= corr0;
            o[nt*4+2] *= corr1; o[nt*4+3] *= corr1;
        }
        m0 = mn0; m1 = mn1;

        // ---- P: C-fragment == A-fragment, pack in registers ----
        unsigned ah[4], al[4];
        bfsplit2(p[0][0], p[0][1], ah[0], al[0]);   // (r4,   k=2q4,2q4+1)
        bfsplit2(p[0][2], p[0][3], ah[1], al[1]);   // (r4+8, k=2q4,2q4+1)
        bfsplit2(p[1][0], p[1][1], ah[2], al[2]);   // (r4,   k=8+2q4,..)
        bfsplit2(p[1][2], p[1][3], ah[3], al[3]);   // (r4+8, k=8+2q4,..)

        // ---- O[16h x 64d] += P V, V fragments straight from global ----
        int vkey = kbase + w*16 + d0q;
#pragma unroll
        for (int nt = 0; nt < 8; nt++) {
            size_t vo = (size_t)(nt*8 + r4) * TT + vkey;
            unsigned bh0 = *(const unsigned*)&g_vhT[vo];
            unsigned bh1 = *(const unsigned*)&g_vhT[vo + 8];
            unsigned bl0 = *(const unsigned*)&g_vlT[vo];
            unsigned bl1 = *(const unsigned*)&g_vlT[vo + 8];
            mma16(&o[nt*4], ah, bh0, bh1);
            mma16(&o[nt*4], ah, bl0, bl1);
            mma16(&o[nt*4], al, bh0, bh1);
        }
    }

    // ---- merge 4 per-warp partials ----
    __syncthreads();
    float* mo = sbuf;                 // [w][16][66]
    float* ml = sbuf + 4224;          // [w][16][2] (m,l)
#pragma unroll
    for (int nt = 0; nt < 8; nt++) {
        *(float2*)&mo[(w*16 + r4)*66   + nt*8 + 2*q4] = make_float2(o[nt*4+0], o[nt*4+1]);
        *(float2*)&mo[(w*16 + r4+8)*66 + nt*8 + 2*q4] = make_float2(o[nt*4+2], o[nt*4+3]);
    }
    if (q4 == 0) {
        ml[w*32 + r4*2]       = m0; ml[w*32 + r4*2 + 1]       = l0;
        ml[w*32 + (r4+8)*2]   = m1; ml[w*32 + (r4+8)*2 + 1]   = l1;
    }
    __syncthreads();
    for (int i = tid; i < 1024; i += 128) {
        int h = i >> 6, d = i & 63;
        float ms = fmaxf(fmaxf(ml[h*2], ml[32 + h*2]),
                         fmaxf(ml[64 + h*2], ml[96 + h*2]));
        float li = 0.f, oi = 0.f;
#pragma unroll
        for (int ww = 0; ww < 4; ww++) {
            float ew = __expf(ml[ww*32 + h*2] - ms);
            li += ml[ww*32 + h*2 + 1] * ew;
            oi += mo[(ww*16 + h)*66 + d] * ew;
        }
        float gs = 1.f/(1.f + __expf(-g_gate[t*48 + h*3 + 1]));
        size_t ob = (size_t)t*1024 + i;
        g_o[ob] = oi * gs / li + g_ocmp[ob];
    }
}

// ======================================================================
extern "C" void kernel_launch(void* const* d_in, const int* in_sizes, int n_in,
                              void* d_out, int out_size)
{
    const float* x  = (const float*)d_in[0];
    const float* Wq = (const float*)d_in[1];
    const float* Wk = (const float*)d_in[2];
    const float* Wv = (const float*)d_in[3];
    const float* Wg = (const float*)d_in[4];
    const float* Wo = (const float*)d_in[5];
    float* out = (float*)d_out;

    proj_gemm_kernel<<<dim3(16, 16, 4), 256>>>(x, Wq, Wk, Wv, Wg);
    pool_kernel<<<32, 64>>>();
    split_kv_kernel<<<512, 256>>>();
    cmp_attn_kernel<<<2048, 256>>>();
    sel_attn_kernel<<<2072, 128>>>();
    out_gemm_kernel<<<dim3(16, 16, 1), 256>>>(Wo, out);
}